// round 8
// baseline (speedup 1.0000x reference)
#include <cuda_runtime.h>
#include <cstdint>

#define NMAX 1000000
#define NE 4
#define DD 128
#define HH 128

#define LDA 132   // 132 % 32 == 4 -> A-fragment LDS conflict-free

// scratch (no allocation allowed -> device globals)
__device__ int g_cursor[NE];
__device__ int g_sorted[NE * NMAX];

// ============================ helpers ============================
__device__ __forceinline__ uint32_t smem_u32(const void* p){
    uint32_t r;
    asm("{ .reg .u64 t; cvta.to.shared.u64 t, %1; cvt.u32.u64 %0, t; }" : "=r"(r) : "l"(p));
    return r;
}
__device__ __forceinline__ uint32_t f2tf32(float f){
    uint32_t r;
    asm("cvt.rna.tf32.f32 %0, %1;" : "=r"(r) : "f"(f));
    return r;
}
__device__ __forceinline__ void cp_async16(uint32_t daddr, const void* src){
    asm volatile("cp.async.cg.shared.global [%0], [%1], 16;" :: "r"(daddr), "l"(src) : "memory");
}
#define CP_COMMIT() asm volatile("cp.async.commit_group;" ::: "memory")
#define CP_WAIT0()  asm volatile("cp.async.wait_group 0;"  ::: "memory")

__device__ __forceinline__ void mma_tf32(float c[4],
                                         uint32_t a0, uint32_t a1, uint32_t a2, uint32_t a3,
                                         uint32_t b0, uint32_t b1){
    asm volatile(
        "mma.sync.aligned.m16n8k8.row.col.f32.tf32.tf32.f32 "
        "{%0,%1,%2,%3}, {%4,%5,%6,%7}, {%8,%9}, {%0,%1,%2,%3};"
        : "+f"(c[0]), "+f"(c[1]), "+f"(c[2]), "+f"(c[3])
        : "r"(a0), "r"(a1), "r"(a2), "r"(a3), "r"(b0), "r"(b1));
}

// ============================ bucketing ============================
__global__ void assign_kernel(const int* __restrict__ element, int n){
    __shared__ int wcnt[8][NE];
    __shared__ int woff[8][NE];
    __shared__ int bbase[NE];
    int tid = threadIdx.x, lane = tid & 31, w = tid >> 5;
    int i = blockIdx.x * 256 + tid;
    int e = (i < n) ? element[i] : -1;
    int rank = 0;
    #pragma unroll
    for (int ee = 0; ee < NE; ee++){
        unsigned m = __ballot_sync(0xFFFFFFFFu, e == ee);
        if (lane == 0) wcnt[w][ee] = __popc(m);
        if (e == ee) rank = __popc(m & ((1u << lane) - 1u));
    }
    __syncthreads();
    if (tid < NE){
        int s = 0;
        #pragma unroll
        for (int ww = 0; ww < 8; ww++){ int c = wcnt[ww][tid]; woff[ww][tid] = s; s += c; }
        bbase[tid] = s ? atomicAdd(&g_cursor[tid], s) : 0;
    }
    __syncthreads();
    if (e >= 0){
        int slot = bbase[e] + woff[w][e] + rank;
        g_sorted[e * NMAX + slot] = i;
    }
}

// ============================ main GEMM ============================
__global__ __launch_bounds__(512, 1)
void gemm_kernel(const float* __restrict__ desc,
                 const float* __restrict__ W1,
                 const float* __restrict__ b1,
                 const float* __restrict__ W2,
                 const float* __restrict__ b2,
                 float* __restrict__ out)
{
    extern __shared__ float dyn[];
    float* sA  = dyn;                    // 2 x [128 x LDA] raw fp32 A (MMA truncates to tf32)
    float* sBq = dyn + 2 * 128 * LDA;    // B quads: float4[((ks*8 + wn*2 + g)*8 + l4)*4 + lm4]

    __shared__ int   s_idx[2][128];
    __shared__ float s_part[128][4];
    __shared__ float s_b1e[HH], s_w2e[HH];
    __shared__ float s_b2e;

    const int tid  = threadIdx.x;
    const int wid  = tid >> 5;
    const int lane = tid & 31;
    const int l4   = lane >> 2;   // groupID (0..7)
    const int lm4  = lane & 3;    // threadID in group
    const int wm   = wid & 3;     // M group (32 rows)
    const int wn   = wid >> 2;    // N group (32 cols)
    const int kofs = (wid >> 2) << 2;   // per-SMSP-slot k-phase offset: 0,4,8,12

    int cnt[NE], tstart[NE + 1];
    tstart[0] = 0;
    #pragma unroll
    for (int e = 0; e < NE; e++){
        cnt[e] = g_cursor[e];
        tstart[e + 1] = tstart[e] + ((cnt[e] + 127) >> 7);
    }
    const int total = tstart[NE];
    const int chunk = (total + (int)gridDim.x - 1) / (int)gridDim.x;
    const int t0 = blockIdx.x * chunk;
    const int t1 = min(total, t0 + chunk);

    if (t0 < t1) {
        auto expert_of = [&](int t){ int e = 0; while (t >= tstart[e + 1]) e++; return e; };

        auto load_expert = [&](int e){
            const float* W1e = W1 + (size_t)e * DD * HH;
            for (int v = tid; v < DD * HH; v += 512){
                int k = v >> 7, col = v & 127;       // W1[e][k][col], coalesced over col
                int ks = k >> 3, kk = k & 7;
                int lm4b = kk & 3, half = kk >> 2;
                int wnb = col >> 5, rem = col & 31;
                int g = rem >> 4, w16 = rem & 15, m = w16 >> 3, l4b = w16 & 7;
                int fidx = ((((ks * 8 + wnb * 2 + g) * 8 + l4b) * 4 + lm4b) << 2) + 2 * m + half;
                sBq[fidx] = __uint_as_float(f2tf32(W1e[v]));
            }
            if (tid < HH){
                s_b1e[tid] = b1[e * HH + tid];
                s_w2e[tid] = W2[e * HH + tid];
            }
            if (tid == 0) s_b2e = b2[e];
        };

        auto gather = [&](int t, int e, int buf){
            int trow = (t - tstart[e]) << 7;
            int rows = min(128, cnt[e] - trow);
            const int* bidx = g_sorted + e * NMAX + trow;
            if (tid < 128) s_idx[buf][tid] = (tid < rows) ? bidx[tid] : -1;
            float* A = sA + buf * (128 * LDA);
            #pragma unroll 8
            for (int v = tid; v < 128 * 32; v += 512){
                int row = v >> 5, seg = v & 31;
                float* dst = A + row * LDA + seg * 4;
                if (row < rows){
                    int a = __ldg(bidx + row);
                    cp_async16(smem_u32(dst), desc + (size_t)a * DD + seg * 4);
                } else {
                    *(float4*)dst = make_float4(0.f, 0.f, 0.f, 0.f);
                }
            }
            CP_COMMIT();
        };

        int cur_e = expert_of(t0);
        load_expert(cur_e);
        gather(t0, cur_e, 0);
        CP_WAIT0();
        __syncthreads();

        for (int t = t0; t < t1; ++t){
            const int buf = (t - t0) & 1;

            // prefetch next tile (same expert) — overlaps with MMA below
            const int tn = t + 1;
            const bool have_next = tn < t1;
            const int e_next = have_next ? expert_of(tn) : -1;
            const bool same = have_next && (e_next == cur_e);
            if (same) gather(tn, cur_e, buf ^ 1);

            // ---- MMA: D[128x128] = A[128x128] @ W1^T ----
            float acc[2][4][4];
            #pragma unroll
            for (int mb = 0; mb < 2; mb++)
                #pragma unroll
                for (int nb = 0; nb < 4; nb++)
                    #pragma unroll
                    for (int i = 0; i < 4; i++) acc[mb][nb][i] = 0.f;

            const float* A = sA + buf * (128 * LDA);
            const float4* Bq = (const float4*)sBq;

            auto mma_step = [&](int ks){
                const int k0 = ks * 8;
                uint32_t a[2][4];
                #pragma unroll
                for (int mb = 0; mb < 2; mb++){
                    const float* ap = A + (32 * wm + 16 * mb + l4) * LDA + k0 + lm4;
                    a[mb][0] = __float_as_uint(ap[0]);            // raw fp32 bits ->
                    a[mb][1] = __float_as_uint(ap[8 * LDA]);      // tf32 truncation in HW
                    a[mb][2] = __float_as_uint(ap[4]);
                    a[mb][3] = __float_as_uint(ap[8 * LDA + 4]);
                }
                uint32_t b[4][2];
                #pragma unroll
                for (int g = 0; g < 2; g++){
                    float4 bv = Bq[(((ks * 8 + wn * 2 + g) * 8 + l4) << 2) + lm4];
                    b[2 * g + 0][0] = __float_as_uint(bv.x);
                    b[2 * g + 0][1] = __float_as_uint(bv.y);
                    b[2 * g + 1][0] = __float_as_uint(bv.z);
                    b[2 * g + 1][1] = __float_as_uint(bv.w);
                }
                #pragma unroll
                for (int mb = 0; mb < 2; mb++)
                    #pragma unroll
                    for (int nb = 0; nb < 4; nb++)
                        mma_tf32(acc[mb][nb], a[mb][0], a[mb][1], a[mb][2], a[mb][3],
                                 b[nb][0], b[nb][1]);
            };

            // per-warp k-phase rotation: start at kofs, wrap via second loop
            #pragma unroll 4
            for (int ks = kofs; ks < 16; ks++) mma_step(ks);
            #pragma unroll 4
            for (int ks = 0; ks < kofs; ks++) mma_step(ks);

            // ---- epilogue: y[row] = sum_col relu(d + b1[col]) * w2[col] ----
            #pragma unroll
            for (int mb = 0; mb < 2; mb++){
                #pragma unroll
                for (int half = 0; half < 2; half++){
                    float p = 0.f;
                    #pragma unroll
                    for (int nb = 0; nb < 4; nb++){
                        int col = 32 * wn + 8 * nb + 2 * lm4;
                        float2 bb1 = *(const float2*)&s_b1e[col];
                        float2 ww2 = *(const float2*)&s_w2e[col];
                        float h0 = fmaxf(acc[mb][nb][2 * half + 0] + bb1.x, 0.f);
                        float h1 = fmaxf(acc[mb][nb][2 * half + 1] + bb1.y, 0.f);
                        p = fmaf(h0, ww2.x, p);
                        p = fmaf(h1, ww2.y, p);
                    }
                    p += __shfl_xor_sync(0xFFFFFFFFu, p, 1);
                    p += __shfl_xor_sync(0xFFFFFFFFu, p, 2);
                    if (lm4 == 0){
                        int row = 32 * wm + 16 * mb + 8 * half + l4;
                        s_part[row][wn] = p;
                    }
                }
            }
            __syncthreads();
            if (tid < 128){
                int a = s_idx[buf][tid];
                if (a >= 0)
                    out[a] = (s_part[tid][0] + s_part[tid][1])
                           + (s_part[tid][2] + s_part[tid][3]) + s_b2e;
            }

            // expert switch: all warps are past the MMA (post-epilogue sync)
            if (have_next && !same){
                __syncthreads();
                cur_e = e_next;
                load_expert(cur_e);
                gather(tn, cur_e, buf ^ 1);
            }

            CP_WAIT0();
            __syncthreads();
        }
    }

    // reset bucket cursors for the next replay (grid=148 is one wave, so all
    // CTAs snapshot g_cursor at entry before block 0 finishes)
    if (blockIdx.x == 0 && threadIdx.x < NE) g_cursor[threadIdx.x] = 0;
}

// ============================ launch ============================
extern "C" void kernel_launch(void* const* d_in, const int* in_sizes, int n_in,
                              void* d_out, int out_size)
{
    const int*   element = (const int*)d_in[0];
    const float* desc    = (const float*)d_in[1];
    const float* W1      = (const float*)d_in[2];
    const float* b1      = (const float*)d_in[3];
    const float* W2      = (const float*)d_in[4];
    const float* b2      = (const float*)d_in[5];
    float* out = (float*)d_out;
    int n = in_sizes[0];

    const int DYN = (2 * 128 * LDA + DD * HH) * (int)sizeof(float);  // 200704 B
    cudaFuncSetAttribute(gemm_kernel, cudaFuncAttributeMaxDynamicSharedMemorySize, DYN);

    assign_kernel<<<(n + 255) / 256, 256>>>(element, n);
    gemm_kernel<<<148, 512, DYN>>>(desc, W1, b1, W2, b2, out);
}

// round 10
// speedup vs baseline: 1.2411x; 1.2411x over previous
#include <cuda_runtime.h>
#include <cuda_fp16.h>
#include <cstdint>

#define NMAX 1000000
#define NE 4
#define DD 128
#define HH 128

#define LDS_F 132   // staging fp32 stride (words): 132 % 32 == 4

// scratch (no allocation allowed -> device globals)
__device__ int g_cursor[NE];
__device__ int g_sorted[NE * NMAX];

// ============================ helpers ============================
__device__ __forceinline__ uint32_t smem_u32(const void* p){
    uint32_t r;
    asm("{ .reg .u64 t; cvta.to.shared.u64 t, %1; cvt.u32.u64 %0, t; }" : "=r"(r) : "l"(p));
    return r;
}
__device__ __forceinline__ uint32_t pack_f16x2(float lo, float hi){
    uint32_t r;
    asm("cvt.rn.f16x2.f32 %0, %1, %2;" : "=r"(r) : "f"(hi), "f"(lo));
    return r;
}
__device__ __forceinline__ void cp_async16(uint32_t daddr, const void* src){
    asm volatile("cp.async.cg.shared.global [%0], [%1], 16;" :: "r"(daddr), "l"(src) : "memory");
}
#define CP_COMMIT() asm volatile("cp.async.commit_group;" ::: "memory")
#define CP_WAIT0()  asm volatile("cp.async.wait_group 0;"  ::: "memory")

__device__ __forceinline__ void mma_f16(float c[4],
                                        uint32_t a0, uint32_t a1, uint32_t a2, uint32_t a3,
                                        uint32_t b0, uint32_t b1){
    asm volatile(
        "mma.sync.aligned.m16n8k16.row.col.f32.f16.f16.f32 "
        "{%0,%1,%2,%3}, {%4,%5,%6,%7}, {%8,%9}, {%0,%1,%2,%3};"
        : "+f"(c[0]), "+f"(c[1]), "+f"(c[2]), "+f"(c[3])
        : "r"(a0), "r"(a1), "r"(a2), "r"(a3), "r"(b0), "r"(b1));
}

// ============================ bucketing ============================
__global__ void assign_kernel(const int* __restrict__ element, int n){
    __shared__ int wcnt[8][NE];
    __shared__ int woff[8][NE];
    __shared__ int bbase[NE];
    int tid = threadIdx.x, lane = tid & 31, w = tid >> 5;
    int i = blockIdx.x * 256 + tid;
    int e = (i < n) ? element[i] : -1;
    int rank = 0;
    #pragma unroll
    for (int ee = 0; ee < NE; ee++){
        unsigned m = __ballot_sync(0xFFFFFFFFu, e == ee);
        if (lane == 0) wcnt[w][ee] = __popc(m);
        if (e == ee) rank = __popc(m & ((1u << lane) - 1u));
    }
    __syncthreads();
    if (tid < NE){
        int s = 0;
        #pragma unroll
        for (int ww = 0; ww < 8; ww++){ int c = wcnt[ww][tid]; woff[ww][tid] = s; s += c; }
        bbase[tid] = s ? atomicAdd(&g_cursor[tid], s) : 0;
    }
    __syncthreads();
    if (e >= 0){
        int slot = bbase[e] + woff[w][e] + rank;
        g_sorted[e * NMAX + slot] = i;
    }
}

// ============================ main GEMM (fp16 MMA, fp32 accum) ============
__global__ __launch_bounds__(512, 1)
void gemm_kernel(const float* __restrict__ desc,
                 const float* __restrict__ W1,
                 const float* __restrict__ b1,
                 const float* __restrict__ W2,
                 const float* __restrict__ b2,
                 float* __restrict__ out)
{
    extern __shared__ float dyn[];
    float*    sStg = dyn;                              // [128 x LDS_F] fp32 staging (single)
    uint32_t* sAh  = (uint32_t*)(dyn + 128 * LDS_F);   // 2 x [128 x 68] f16x2 words
    float4*   sBq  = (float4*)(sAh + 2 * 128 * 68);    // packed B f16 quads (2048 float4)

    __shared__ int   s_idx[2][128];
    __shared__ float s_part[128][4];
    __shared__ float s_b1e[HH], s_w2e[HH];
    __shared__ float s_b2e;

    const int tid  = threadIdx.x;
    const int wid  = tid >> 5;
    const int lane = tid & 31;
    const int l4   = lane >> 2;   // groupID (0..7)
    const int lm4  = lane & 3;    // threadID in group
    const int wm   = wid & 3;     // M group (32 rows)
    const int wn   = wid >> 2;    // N group (32 cols)

    int cnt[NE], tstart[NE + 1];
    tstart[0] = 0;
    #pragma unroll
    for (int e = 0; e < NE; e++){
        cnt[e] = g_cursor[e];
        tstart[e + 1] = tstart[e] + ((cnt[e] + 127) >> 7);
    }
    const int total = tstart[NE];
    const int chunk = (total + (int)gridDim.x - 1) / (int)gridDim.x;
    const int t0 = blockIdx.x * chunk;
    const int t1 = min(total, t0 + chunk);

    if (t0 < t1) {
        auto expert_of = [&](int t){ int e = 0; while (t >= tstart[e + 1]) e++; return e; };

        auto load_expert = [&](int e){
            const float* W1e = W1 + (size_t)e * DD * HH;
            __half* sBh = (__half*)sBq;
            for (int v = tid; v < DD * HH; v += 512){
                int k = v >> 7, col = v & 127;       // W1[e][k][col]
                int ks = k >> 4, kk = k & 15;
                int lm4b = (kk & 7) >> 1, ddb = kk & 1, hb = kk >> 3;
                int wnb = col >> 5, rem = col & 31;
                int nbb = rem >> 3, l4b = rem & 7;
                int q = nbb >> 1, slot = (nbb & 1) * 2 + hb;
                int inner = ((l4b >> 1) << 3) + (lm4b << 1) + (l4b & 1);   // 0..31 bijection
                int idx128 = ((ks * 4 + wnb) * 2 + q) * 32 + inner;
                sBh[idx128 * 8 + slot * 2 + ddb] = __float2half_rn(W1e[v]);
            }
            if (tid < HH){
                s_b1e[tid] = b1[e * HH + tid];
                s_w2e[tid] = W2[e * HH + tid];
            }
            if (tid == 0) s_b2e = b2[e];
        };

        auto gather = [&](int t, int e, int buf){
            int trow = (t - tstart[e]) << 7;
            int rows = min(128, cnt[e] - trow);
            const int* bidx = g_sorted + e * NMAX + trow;
            if (tid < 128) s_idx[buf][tid] = (tid < rows) ? bidx[tid] : -1;
            #pragma unroll 8
            for (int v = tid; v < 128 * 32; v += 512){
                int row = v >> 5, seg = v & 31;
                float* dst = sStg + row * LDS_F + seg * 4;
                if (row < rows){
                    int a = __ldg(bidx + row);
                    cp_async16(smem_u32(dst), desc + (size_t)a * DD + seg * 4);
                } else {
                    *(float4*)dst = make_float4(0.f, 0.f, 0.f, 0.f);
                }
            }
            CP_COMMIT();
        };

        // staging fp32 -> f16x2 words in sAh[buf] (rn conversion)
        auto convert = [&](int buf){
            uint32_t* Ah = sAh + buf * (128 * 68);
            #pragma unroll 8
            for (int v = tid; v < 128 * 32; v += 512){
                int row = v >> 5, seg = v & 31;
                float4 f = *(const float4*)(sStg + row * LDS_F + seg * 4);
                uint32_t lo = pack_f16x2(f.x, f.y);
                uint32_t hi = pack_f16x2(f.z, f.w);
                uint2* dst = (uint2*)(Ah + row * 68 + seg * 2);
                *dst = make_uint2(lo, hi);
            }
        };

        int cur_e = expert_of(t0);
        load_expert(cur_e);
        gather(t0, cur_e, 0);
        CP_WAIT0();
        __syncthreads();
        convert(0);
        __syncthreads();

        for (int t = t0; t < t1; ++t){
            const int buf = (t - t0) & 1;

            // prefetch next tile into staging (async during MMA)
            const int tn = t + 1;
            const bool have_next = tn < t1;
            const int e_next = have_next ? expert_of(tn) : -1;
            const bool same = have_next && (e_next == cur_e);
            if (same) gather(tn, cur_e, buf ^ 1);

            // ---- MMA: D[128x128] = A[128x128] @ W1^T (f16 operands) ----
            float acc[2][4][4];
            #pragma unroll
            for (int mb = 0; mb < 2; mb++)
                #pragma unroll
                for (int nb = 0; nb < 4; nb++)
                    #pragma unroll
                    for (int i = 0; i < 4; i++) acc[mb][nb][i] = 0.f;

            const uint32_t* Ah = sAh + buf * (128 * 68);
            const int innerB = ((l4 >> 1) << 3) + (lm4 << 1) + (l4 & 1);

            #pragma unroll 8
            for (int ks = 0; ks < 8; ks++){     // k16 per step
                uint32_t a[2][4];
                #pragma unroll
                for (int mb = 0; mb < 2; mb++){
                    const uint32_t* ap = Ah + (32 * wm + 16 * mb + l4) * 68 + ks * 8 + lm4;
                    a[mb][0] = ap[0];           // rows l4 / l4+8, k halves 2lm4.. / +8
                    a[mb][1] = ap[8 * 68];
                    a[mb][2] = ap[4];
                    a[mb][3] = ap[8 * 68 + 4];
                }
                uint32_t b[4][2];
                const float4* bp = sBq + ((ks * 4 + wn) * 2) * 32 + innerB;
                float4 bq0 = bp[0];
                float4 bq1 = bp[32];
                b[0][0] = __float_as_uint(bq0.x); b[0][1] = __float_as_uint(bq0.y);
                b[1][0] = __float_as_uint(bq0.z); b[1][1] = __float_as_uint(bq0.w);
                b[2][0] = __float_as_uint(bq1.x); b[2][1] = __float_as_uint(bq1.y);
                b[3][0] = __float_as_uint(bq1.z); b[3][1] = __float_as_uint(bq1.w);
                #pragma unroll
                for (int mb = 0; mb < 2; mb++)
                    #pragma unroll
                    for (int nb = 0; nb < 4; nb++)
                        mma_f16(acc[mb][nb], a[mb][0], a[mb][1], a[mb][2], a[mb][3],
                                b[nb][0], b[nb][1]);
            }

            // ---- epilogue: y[row] = sum_col relu(d + b1[col]) * w2[col] ----
            #pragma unroll
            for (int mb = 0; mb < 2; mb++){
                #pragma unroll
                for (int half = 0; half < 2; half++){
                    float p = 0.f;
                    #pragma unroll
                    for (int nb = 0; nb < 4; nb++){
                        int col = 32 * wn + 8 * nb + 2 * lm4;
                        float2 bb1 = *(const float2*)&s_b1e[col];
                        float2 ww2 = *(const float2*)&s_w2e[col];
                        float h0 = fmaxf(acc[mb][nb][2 * half + 0] + bb1.x, 0.f);
                        float h1 = fmaxf(acc[mb][nb][2 * half + 1] + bb1.y, 0.f);
                        p = fmaf(h0, ww2.x, p);
                        p = fmaf(h1, ww2.y, p);
                    }
                    p += __shfl_xor_sync(0xFFFFFFFFu, p, 1);
                    p += __shfl_xor_sync(0xFFFFFFFFu, p, 2);
                    if (lm4 == 0){
                        int row = 32 * wm + 16 * mb + 8 * half + l4;
                        s_part[row][wn] = p;
                    }
                }
            }
            __syncthreads();
            if (tid < 128){
                int a = s_idx[buf][tid];
                if (a >= 0)
                    out[a] = (s_part[tid][0] + s_part[tid][1])
                           + (s_part[tid][2] + s_part[tid][3]) + s_b2e;
            }

            if (have_next){
                if (!same){
                    __syncthreads();
                    cur_e = e_next;
                    load_expert(cur_e);
                    gather(tn, cur_e, buf ^ 1);
                }
                CP_WAIT0();
                __syncthreads();          // staging complete + epilogue reads done
                convert(buf ^ 1);
                __syncthreads();          // sAh[buf^1] ready for next MMA
            }
        }
    }

    // reset bucket cursors for the next replay (grid=148 is one wave, so all
    // CTAs snapshot g_cursor at entry before block 0 finishes)
    if (blockIdx.x == 0 && threadIdx.x < NE) g_cursor[threadIdx.x] = 0;
}

// ============================ launch ============================
extern "C" void kernel_launch(void* const* d_in, const int* in_sizes, int n_in,
                              void* d_out, int out_size)
{
    const int*   element = (const int*)d_in[0];
    const float* desc    = (const float*)d_in[1];
    const float* W1      = (const float*)d_in[2];
    const float* b1      = (const float*)d_in[3];
    const float* W2      = (const float*)d_in[4];
    const float* b2      = (const float*)d_in[5];
    float* out = (float*)d_out;
    int n = in_sizes[0];

    // staging 128*132*4 + A-f16 2*128*68*4 + B-f16 2048*16 = 67584+69632+32768
    const int DYN = 128 * LDS_F * 4 + 2 * 128 * 68 * 4 + 2048 * 16;  // 169984 B
    cudaFuncSetAttribute(gemm_kernel, cudaFuncAttributeMaxDynamicSharedMemorySize, DYN);

    assign_kernel<<<(n + 255) / 256, 256>>>(element, n);
    gemm_kernel<<<148, 512, DYN>>>(desc, W1, b1, W2, b2, out);
}